// round 10
// baseline (speedup 1.0000x reference)
#include <cuda_runtime.h>
#include <stdint.h>

// EGCN pull-mode: build CSR-by-dst on device, then per-node register aggregation.
// x0 = l2norm(emb); x1 = A x0; out = x0 + x1 + A x1   (A = weighted adjacency)
// N=100000, DIM=64, E=1.6M. adj arrives int32.

constexpr int N_NODES = 100000;
constexpr int DIM     = 64;
constexpr int DIM4    = DIM / 4;     // 16 float4 per row
constexpr int MAX_E   = 1600000;
constexpr int SCAN_B  = 512;                                  // elems per scan block
constexpr int NUM_SB  = (N_NODES + SCAN_B - 1) / SCAN_B;      // 196 scan blocks

// ---- device scratch (allocation-free contract) ----
__device__ float4 g_x0[(long long)N_NODES * DIM4];
__device__ float4 g_x1[(long long)N_NODES * DIM4];
__device__ int    g_cnt[N_NODES];        // in-degree histogram
__device__ int    g_off[N_NODES + 1];    // exclusive offsets
__device__ int    g_cur[N_NODES];        // scatter cursors
__device__ int    g_bsum[256];           // scan block sums
__device__ int2   g_edge[MAX_E];         // {src, w_bits} sorted by dst

// ---------------------------------------------------------------------------
// 1) normalize rows into g_x0; also zero histogram counters.
// (N_NODES*16 threads; divides 256 exactly -> no intra-warp early exit.)
// ---------------------------------------------------------------------------
__global__ __launch_bounds__(256) void normalize_kernel(const float4* __restrict__ emb) {
    int tid  = blockIdx.x * blockDim.x + threadIdx.x;
    int row  = tid >> 4;
    int lane = tid & 15;
    if (row < N_NODES && lane == 0) g_cnt[row] = 0;
    if (row >= N_NODES) return;

    long long idx = (long long)row * DIM4 + lane;
    float4 v = emb[idx];
    float ss = v.x * v.x + v.y * v.y + v.z * v.z + v.w * v.w;
    #pragma unroll
    for (int o = 8; o; o >>= 1) ss += __shfl_xor_sync(0xffffffffu, ss, o, 16);
    float inv = 1.0f / fmaxf(sqrtf(ss), 1e-12f);
    g_x0[idx] = make_float4(v.x * inv, v.y * inv, v.z * inv, v.w * inv);
}

// ---------------------------------------------------------------------------
// 2) histogram of dst
// ---------------------------------------------------------------------------
__global__ __launch_bounds__(256) void hist_kernel(const int* __restrict__ adj, int num_edges) {
    int e = blockIdx.x * blockDim.x + threadIdx.x;
    if (e >= num_edges) return;
    atomicAdd(&g_cnt[adj[num_edges + e]], 1);
}

// ---------------------------------------------------------------------------
// 3a) per-block exclusive scan of g_cnt -> g_off, block totals -> g_bsum
// ---------------------------------------------------------------------------
__global__ __launch_bounds__(SCAN_B) void scan_block_kernel() {
    __shared__ int warp_sums[SCAN_B / 32];   // 16
    int t    = threadIdx.x;
    int gid  = blockIdx.x * SCAN_B + t;
    int lane = t & 31, wid = t >> 5;

    int v = (gid < N_NODES) ? g_cnt[gid] : 0;
    int x = v;
    #pragma unroll
    for (int o = 1; o < 32; o <<= 1) {
        int y = __shfl_up_sync(0xffffffffu, x, o);
        if (lane >= o) x += y;
    }
    if (lane == 31) warp_sums[wid] = x;
    __syncthreads();
    // Second-level scan: ALL 32 lanes of warp 0 execute the shuffles
    // (lanes >= 16 carry 0); only lanes < 16 store. Full-mask-safe.
    if (wid == 0) {
        int s = (lane < SCAN_B / 32) ? warp_sums[lane] : 0;
        #pragma unroll
        for (int o = 1; o < SCAN_B / 32; o <<= 1) {
            int y = __shfl_up_sync(0xffffffffu, s, o);
            if (lane >= o) s += y;
        }
        if (lane < SCAN_B / 32) warp_sums[lane] = s;
    }
    __syncthreads();
    int prefix = (wid > 0) ? warp_sums[wid - 1] : 0;
    int incl   = prefix + x;
    if (gid < N_NODES) g_off[gid] = incl - v;
    if (t == SCAN_B - 1) g_bsum[blockIdx.x] = incl;
}

// ---------------------------------------------------------------------------
// 3b) fixup WITH inline block-sum scan: every block re-scans the 196 block
// sums in shared (cheap, L2-resident), then applies its prefix. Also inits
// cursors and g_off[N]. Replaces the former single-block scan_sums launch.
// ---------------------------------------------------------------------------
__global__ __launch_bounds__(256) void scan_fixup_kernel(int num_edges) {
    __shared__ int sh[256];
    int t = threadIdx.x;
    int v = (t < NUM_SB) ? g_bsum[t] : 0;
    sh[t] = v;
    __syncthreads();
    #pragma unroll
    for (int o = 1; o < 256; o <<= 1) {
        int y = (t >= o) ? sh[t - o] : 0;
        __syncthreads();
        sh[t] += y;
        __syncthreads();
    }
    // sh[] now inclusive scan of block sums; exclusive prefix for scan-block
    // k is sh[k-1] (0 for k==0).
    int i = blockIdx.x * 256 + t;
    if (i < N_NODES) {
        int k   = i / SCAN_B;
        int add = (k > 0) ? sh[k - 1] : 0;
        int o   = g_off[i] + add;
        g_off[i] = o;
        g_cur[i] = o;
        if (i == 0) g_off[N_NODES] = num_edges;
    }
}

// ---------------------------------------------------------------------------
// 4) scatter edges into dst-sorted order: g_edge[pos] = {src, w}
// ---------------------------------------------------------------------------
__global__ __launch_bounds__(256) void scatter_kernel(
    const int* __restrict__ adj, const float* __restrict__ wvec, int num_edges) {
    int e = blockIdx.x * blockDim.x + threadIdx.x;
    if (e >= num_edges) return;
    int dst = adj[num_edges + e];
    int pos = atomicAdd(&g_cur[dst], 1);
    g_edge[pos] = make_int2(adj[e], __float_as_int(wvec[e]));
}

// ---------------------------------------------------------------------------
// 5) pull layer: one warp per node. Stage up to 32 edge records per warp in
// registers (one coalesced 256B load), then process 2 edges per step via
// register shuffles — gather addresses never depend on an in-flight load,
// and unroll-4 keeps ~4 independent gathers outstanding per warp.
// Lane c owns float4 chunk c; halves handle even/odd edges of each step.
// (N_NODES*32 threads; divides 256 exactly -> whole warps exit together.)
// ---------------------------------------------------------------------------
__global__ __launch_bounds__(256) void pull_layer_kernel(
    const float4* __restrict__ xin,
    float4*       __restrict__ xout,
    const float4* __restrict__ base0,   // nullable
    const float4* __restrict__ base1)   // nullable
{
    int node = (blockIdx.x * blockDim.x + threadIdx.x) >> 5;
    if (node >= N_NODES) return;
    int lane = threadIdx.x & 31;
    int half = lane >> 4;       // 0 or 1
    int c    = lane & 15;       // chunk

    int beg = g_off[node];
    int end = g_off[node + 1];

    float4 acc = make_float4(0.f, 0.f, 0.f, 0.f);
    for (int base = beg; base < end; base += 32) {
        int cnt = min(end - base, 32);                 // warp-uniform
        int2 rec = (lane < cnt) ? g_edge[base + lane] : make_int2(0, 0);
        #pragma unroll 4
        for (int j = 0; j < cnt; j += 2) {             // uniform trip count
            int idx = j + half;                        // <= 31
            int s   = __shfl_sync(0xffffffffu, rec.x, idx);
            int wb  = __shfl_sync(0xffffffffu, rec.y, idx);
            if (idx < cnt) {                           // guard gather only
                float  w = __int_as_float(wb);
                float4 v = xin[(long long)s * DIM4 + c];
                acc.x += v.x * w; acc.y += v.y * w;
                acc.z += v.z * w; acc.w += v.w * w;
            }
        }
    }
    // combine halves (lane c += lane c+16); all 32 lanes reach here.
    acc.x += __shfl_xor_sync(0xffffffffu, acc.x, 16);
    acc.y += __shfl_xor_sync(0xffffffffu, acc.y, 16);
    acc.z += __shfl_xor_sync(0xffffffffu, acc.z, 16);
    acc.w += __shfl_xor_sync(0xffffffffu, acc.w, 16);

    if (half == 0) {
        long long idx = (long long)node * DIM4 + c;
        if (base0) {
            float4 b0 = base0[idx], b1 = base1[idx];
            acc.x += b0.x + b1.x; acc.y += b0.y + b1.y;
            acc.z += b0.z + b1.z; acc.w += b0.w + b1.w;
        }
        xout[idx] = acc;
    }
}

// ---------------------------------------------------------------------------
// kernel_launch
// ---------------------------------------------------------------------------
extern "C" void kernel_launch(void* const* d_in, const int* in_sizes, int n_in,
                              void* d_out, int out_size) {
    const float4* emb = (const float4*)d_in[0]; // [100000, 64] f32
    const float*  wv  = (const float*)d_in[1];  // [E] f32
    const int*    adj = (const int*)d_in[2];    // [2, E] int32

    int E = in_sizes[1];

    float4* x0; float4* x1;
    cudaGetSymbolAddress((void**)&x0, g_x0);
    cudaGetSymbolAddress((void**)&x1, g_x1);
    float4* out4 = reinterpret_cast<float4*>(d_out);

    const int T = 256;

    // 1) normalize + zero counters
    normalize_kernel<<<(N_NODES * 16 + T - 1) / T, T>>>(emb);
    // 2) in-degree histogram
    hist_kernel<<<(E + T - 1) / T, T>>>(adj, E);
    // 3) scan: per-block, then fixup with inline sum-scan
    scan_block_kernel<<<NUM_SB, SCAN_B>>>();
    scan_fixup_kernel<<<(N_NODES + T - 1) / T, T>>>(E);
    // 4) scatter into dst-sorted edge array
    scatter_kernel<<<(E + T - 1) / T, T>>>(adj, wv, E);
    // 5) layer 1: x1 = A x0
    pull_layer_kernel<<<(N_NODES * 32 + T - 1) / T, T>>>(x0, x1, nullptr, nullptr);
    // 6) layer 2 fused: out = x0 + x1 + A x1
    pull_layer_kernel<<<(N_NODES * 32 + T - 1) / T, T>>>(x1, out4, x0, x1);
}

// round 11
// speedup vs baseline: 1.0822x; 1.0822x over previous
#include <cuda_runtime.h>
#include <stdint.h>

// EGCN pull-mode: build CSR-by-dst on device, then per-node register aggregation.
// x0 = l2norm(emb); x1 = A x0; out = x0 + x1 + A x1   (A = weighted adjacency)
// N=100000, DIM=64, E=1.6M. adj arrives int32.

constexpr int N_NODES = 100000;
constexpr int DIM     = 64;
constexpr int DIM4    = DIM / 4;     // 16 float4 per row
constexpr int MAX_E   = 1600000;
constexpr int SCAN_B  = 512;                                  // elems per scan block
constexpr int NUM_SB  = (N_NODES + SCAN_B - 1) / SCAN_B;      // 196 scan blocks

// ---- device scratch (allocation-free contract) ----
__device__ float4 g_x0[(long long)N_NODES * DIM4];
__device__ float4 g_x1[(long long)N_NODES * DIM4];
__device__ int    g_cnt[N_NODES];        // in-degree histogram
__device__ int    g_off[N_NODES + 1];    // exclusive offsets
__device__ int    g_cur[N_NODES];        // scatter cursors
__device__ int    g_bsum[256];           // scan block sums
__device__ int2   g_edge[MAX_E];         // {src, w_bits} sorted by dst

// ---------------------------------------------------------------------------
// 1) normalize rows into g_x0; also zero histogram counters.
// (N_NODES*16 threads; divides 256 exactly -> no intra-warp early exit.)
// ---------------------------------------------------------------------------
__global__ __launch_bounds__(256) void normalize_kernel(const float4* __restrict__ emb) {
    int tid  = blockIdx.x * blockDim.x + threadIdx.x;
    int row  = tid >> 4;
    int lane = tid & 15;
    if (row < N_NODES && lane == 0) g_cnt[row] = 0;
    if (row >= N_NODES) return;

    long long idx = (long long)row * DIM4 + lane;
    float4 v = emb[idx];
    float ss = v.x * v.x + v.y * v.y + v.z * v.z + v.w * v.w;
    #pragma unroll
    for (int o = 8; o; o >>= 1) ss += __shfl_xor_sync(0xffffffffu, ss, o, 16);
    float inv = 1.0f / fmaxf(sqrtf(ss), 1e-12f);
    g_x0[idx] = make_float4(v.x * inv, v.y * inv, v.z * inv, v.w * inv);
}

// ---------------------------------------------------------------------------
// 2) histogram of dst
// ---------------------------------------------------------------------------
__global__ __launch_bounds__(256) void hist_kernel(const int* __restrict__ adj, int num_edges) {
    int e = blockIdx.x * blockDim.x + threadIdx.x;
    if (e >= num_edges) return;
    atomicAdd(&g_cnt[adj[num_edges + e]], 1);
}

// ---------------------------------------------------------------------------
// 3a) per-block exclusive scan of g_cnt -> g_off, block totals -> g_bsum
// ---------------------------------------------------------------------------
__global__ __launch_bounds__(SCAN_B) void scan_block_kernel() {
    __shared__ int warp_sums[SCAN_B / 32];   // 16
    int t    = threadIdx.x;
    int gid  = blockIdx.x * SCAN_B + t;
    int lane = t & 31, wid = t >> 5;

    int v = (gid < N_NODES) ? g_cnt[gid] : 0;
    int x = v;
    #pragma unroll
    for (int o = 1; o < 32; o <<= 1) {
        int y = __shfl_up_sync(0xffffffffu, x, o);
        if (lane >= o) x += y;
    }
    if (lane == 31) warp_sums[wid] = x;
    __syncthreads();
    // Second-level scan: ALL 32 lanes of warp 0 execute the shuffles
    // (lanes >= 16 carry 0); only lanes < 16 store. Full-mask-safe.
    if (wid == 0) {
        int s = (lane < SCAN_B / 32) ? warp_sums[lane] : 0;
        #pragma unroll
        for (int o = 1; o < SCAN_B / 32; o <<= 1) {
            int y = __shfl_up_sync(0xffffffffu, s, o);
            if (lane >= o) s += y;
        }
        if (lane < SCAN_B / 32) warp_sums[lane] = s;
    }
    __syncthreads();
    int prefix = (wid > 0) ? warp_sums[wid - 1] : 0;
    int incl   = prefix + x;
    if (gid < N_NODES) g_off[gid] = incl - v;
    if (t == SCAN_B - 1) g_bsum[blockIdx.x] = incl;
}

// ---------------------------------------------------------------------------
// 3b) fixup WITH inline block-sum scan: every block re-scans the 196 block
// sums in shared, then applies its prefix. Also inits cursors and g_off[N].
// ---------------------------------------------------------------------------
__global__ __launch_bounds__(256) void scan_fixup_kernel(int num_edges) {
    __shared__ int sh[256];
    int t = threadIdx.x;
    int v = (t < NUM_SB) ? g_bsum[t] : 0;
    sh[t] = v;
    __syncthreads();
    #pragma unroll
    for (int o = 1; o < 256; o <<= 1) {
        int y = (t >= o) ? sh[t - o] : 0;
        __syncthreads();
        sh[t] += y;
        __syncthreads();
    }
    // sh[] now inclusive scan of block sums; exclusive prefix for scan-block
    // k is sh[k-1] (0 for k==0).
    int i = blockIdx.x * 256 + t;
    if (i < N_NODES) {
        int k   = i / SCAN_B;
        int add = (k > 0) ? sh[k - 1] : 0;
        int o   = g_off[i] + add;
        g_off[i] = o;
        g_cur[i] = o;
        if (i == 0) g_off[N_NODES] = num_edges;
    }
}

// ---------------------------------------------------------------------------
// 4) scatter edges into dst-sorted order: g_edge[pos] = {src, w}
// ---------------------------------------------------------------------------
__global__ __launch_bounds__(256) void scatter_kernel(
    const int* __restrict__ adj, const float* __restrict__ wvec, int num_edges) {
    int e = blockIdx.x * blockDim.x + threadIdx.x;
    if (e >= num_edges) return;
    int dst = adj[num_edges + e];
    int pos = atomicAdd(&g_cur[dst], 1);
    g_edge[pos] = make_int2(adj[e], __float_as_int(wvec[e]));
}

// ---------------------------------------------------------------------------
// 5) pull layer (R9 form): one warp per node. Lanes split into two 16-lane
// halves processing alternating in-edges; lane c owns float4 chunk c.
// Edge-record addresses depend only on the induction variable, so unroll-4
// lets ptxas batch record loads and keep several gathers in flight.
// (N_NODES*32 threads; divides 256 exactly -> whole warps exit together.)
// ---------------------------------------------------------------------------
__global__ __launch_bounds__(256) void pull_layer_kernel(
    const float4* __restrict__ xin,
    float4*       __restrict__ xout,
    const float4* __restrict__ base0,   // nullable
    const float4* __restrict__ base1)   // nullable
{
    int node = (blockIdx.x * blockDim.x + threadIdx.x) >> 5;
    if (node >= N_NODES) return;
    int lane = threadIdx.x & 31;
    int half = lane >> 4;       // 0 or 1
    int c    = lane & 15;       // chunk

    int beg = g_off[node];
    int end = g_off[node + 1];

    float4 acc = make_float4(0.f, 0.f, 0.f, 0.f);
    #pragma unroll 4
    for (int p = beg + half; p < end; p += 2) {
        int2  ew = g_edge[p];
        float w  = __int_as_float(ew.y);
        float4 v = xin[(long long)ew.x * DIM4 + c];
        acc.x += v.x * w; acc.y += v.y * w; acc.z += v.z * w; acc.w += v.w * w;
    }
    // combine halves (lane c += lane c+16); all 32 lanes reach here.
    acc.x += __shfl_xor_sync(0xffffffffu, acc.x, 16);
    acc.y += __shfl_xor_sync(0xffffffffu, acc.y, 16);
    acc.z += __shfl_xor_sync(0xffffffffu, acc.z, 16);
    acc.w += __shfl_xor_sync(0xffffffffu, acc.w, 16);

    if (half == 0) {
        long long idx = (long long)node * DIM4 + c;
        if (base0) {
            float4 b0 = base0[idx], b1 = base1[idx];
            acc.x += b0.x + b1.x; acc.y += b0.y + b1.y;
            acc.z += b0.z + b1.z; acc.w += b0.w + b1.w;
        }
        xout[idx] = acc;
    }
}

// ---------------------------------------------------------------------------
// kernel_launch
// ---------------------------------------------------------------------------
extern "C" void kernel_launch(void* const* d_in, const int* in_sizes, int n_in,
                              void* d_out, int out_size) {
    const float4* emb = (const float4*)d_in[0]; // [100000, 64] f32
    const float*  wv  = (const float*)d_in[1];  // [E] f32
    const int*    adj = (const int*)d_in[2];    // [2, E] int32

    int E = in_sizes[1];

    float4* x0; float4* x1;
    cudaGetSymbolAddress((void**)&x0, g_x0);
    cudaGetSymbolAddress((void**)&x1, g_x1);
    float4* out4 = reinterpret_cast<float4*>(d_out);

    const int T = 256;

    // 1) normalize + zero counters
    normalize_kernel<<<(N_NODES * 16 + T - 1) / T, T>>>(emb);
    // 2) in-degree histogram
    hist_kernel<<<(E + T - 1) / T, T>>>(adj, E);
    // 3) scan: per-block, then fixup with inline sum-scan
    scan_block_kernel<<<NUM_SB, SCAN_B>>>();
    scan_fixup_kernel<<<(N_NODES + T - 1) / T, T>>>(E);
    // 4) scatter into dst-sorted edge array
    scatter_kernel<<<(E + T - 1) / T, T>>>(adj, wv, E);
    // 5) layer 1: x1 = A x0
    pull_layer_kernel<<<(N_NODES * 32 + T - 1) / T, T>>>(x0, x1, nullptr, nullptr);
    // 6) layer 2 fused: out = x0 + x1 + A x1
    pull_layer_kernel<<<(N_NODES * 32 + T - 1) / T, T>>>(x1, out4, x0, x1);
}